// round 12
// baseline (speedup 1.0000x reference)
#include <cuda_runtime.h>
#include <cuda_fp16.h>
#include <cstdint>
#include <math.h>

// Problem constants
#define N_    1024
#define L_    128
#define WD_   300
#define PD_   50
#define D_    400          // WD + 2*PD
#define FS_   3
#define NF_   512
#define C_    53
#define LP_   126          // L - FS + 1
#define KTOT  1200         // FS * D
#define KPAD  1216         // padded to 19*64
#define KC    64
#define NKC   19
#define NEG_  (-1e30f)
#define F3    (3 * NF_)    // 1536 pooled features
#define CP    64           // padded class column count

// ---------------------------------------------------------------------------
// Scratch (device globals; no allocs allowed)
// ---------------------------------------------------------------------------
__device__ __align__(256) __half g_X[(size_t)N_ * L_ * D_ + 2048];   // fp16 X
__device__ __align__(256) __half g_W[NF_ * KPAD];                    // fp16 W
__device__ float g_feat[(size_t)N_ * F3];        // [n][f*3+seg]
__device__ __align__(256) float g_wT[F3 * CP];   // out_w padded [j][64]

// ---------------------------------------------------------------------------
// Helpers (baseline ISA only: cp.async / ldmatrix / mma.sync)
// ---------------------------------------------------------------------------
__device__ __forceinline__ uint32_t smem_u32(const void* p) {
    uint32_t a;
    asm("{ .reg .u64 t; cvta.to.shared.u64 t, %1; cvt.u32.u64 %0, t; }" : "=r"(a) : "l"(p));
    return a;
}
#define CP_ASYNC16(dst, src) \
    asm volatile("cp.async.cg.shared.global [%0], [%1], 16;" :: "r"(dst), "l"(src) : "memory")
#define CP_COMMIT()  asm volatile("cp.async.commit_group;" ::: "memory")
#define CP_WAIT1()   asm volatile("cp.async.wait_group 1;" ::: "memory")
#define CP_WAIT0()   asm volatile("cp.async.wait_group 0;" ::: "memory")

#define LDSM_X4(d0, d1, d2, d3, addr) \
    asm volatile("ldmatrix.sync.aligned.m8n8.x4.shared.b16 {%0,%1,%2,%3}, [%4];" \
                 : "=r"(d0), "=r"(d1), "=r"(d2), "=r"(d3) : "r"(addr))

#define MMAF16(cc, a0, a1, a2, a3, b0, b1) \
    asm volatile("mma.sync.aligned.m16n8k16.row.col.f32.f16.f16.f32 " \
                 "{%0,%1,%2,%3}, {%4,%5,%6,%7}, {%8,%9}, {%0,%1,%2,%3};" \
                 : "+f"((cc)[0]), "+f"((cc)[1]), "+f"((cc)[2]), "+f"((cc)[3]) \
                 : "r"(a0), "r"(a1), "r"(a2), "r"(a3), "r"(b0), "r"(b1))

// ---------------------------------------------------------------------------
// Kernel 1: embedding gather -> fp16 (2 positions per 256-thread block)
// ---------------------------------------------------------------------------
__global__ __launch_bounds__(256) void gather_kernel(
    const int* __restrict__ tokens, const int* __restrict__ pf1,
    const int* __restrict__ pf2,
    const float* __restrict__ wordvec, const float* __restrict__ pf1_emb,
    const float* __restrict__ pf2_emb)
{
    int id = blockIdx.x * 2 + (threadIdx.x >> 7);   // (n,l)
    int t = threadIdx.x & 127;
    size_t base = (size_t)id * D_;
    if (t < 75) {
        float4 v = reinterpret_cast<const float4*>(wordvec + (size_t)tokens[id] * WD_)[t];
        __half h[4] = {__float2half(v.x), __float2half(v.y),
                       __float2half(v.z), __float2half(v.w)};
        *reinterpret_cast<uint2*>(&g_X[base + t * 4]) = *reinterpret_cast<uint2*>(h);
    } else if (t < 100) {
        int j = t - 75;
        float2 v = reinterpret_cast<const float2*>(pf1_emb + pf1[id] * PD_)[j];
        __half h[2] = {__float2half(v.x), __float2half(v.y)};
        *reinterpret_cast<uint32_t*>(&g_X[base + WD_ + j * 2]) = *reinterpret_cast<uint32_t*>(h);
    } else if (t < 125) {
        int j = t - 100;
        float2 v = reinterpret_cast<const float2*>(pf2_emb + pf2[id] * PD_)[j];
        __half h[2] = {__float2half(v.x), __float2half(v.y)};
        *reinterpret_cast<uint32_t*>(&g_X[base + WD_ + PD_ + j * 2]) = *reinterpret_cast<uint32_t*>(h);
    }
}

// ---------------------------------------------------------------------------
// Kernel 1b: convert conv_w to fp16, zero-padded K 1200->1216
// ---------------------------------------------------------------------------
__global__ __launch_bounds__(256) void wconv_kernel(const float* __restrict__ conv_w)
{
    int idx = blockIdx.x * 256 + threadIdx.x;      // 0 .. NF_*KPAD-1
    int f = idx / KPAD, k = idx % KPAD;
    float v = (k < KTOT) ? conv_w[(size_t)f * KTOT + k] : 0.f;
    g_W[idx] = __float2half(v);
}

// ---------------------------------------------------------------------------
// Kernel 1c: transpose-pad out_w [1536][53] -> g_wT [1536][64] (coalesced)
// ---------------------------------------------------------------------------
__global__ __launch_bounds__(256) void wt_kernel(const float* __restrict__ out_w)
{
    int idx = blockIdx.x * 256 + threadIdx.x;      // 0 .. F3*CP-1
    int j = idx >> 6, c = idx & 63;
    g_wT[idx] = (c < C_) ? out_w[j * C_ + c] : 0.f;
}

// ---------------------------------------------------------------------------
// Kernel 2: mma.sync fp16 conv GEMM (single product) + tanh + pool.
// (byte-identical mainloop to the 563us R11 kernel — proven at HMMA ceiling)
// ---------------------------------------------------------------------------
#define STAGE_SZ 32768
#define B_OFF    16384
#define SM_BIAS  70656
#define SM_DYN   71168
#define RED_STR  132

struct LoadCtx { size_t xbase; int nb; };

__device__ __forceinline__ void load_stage(uint32_t sbase, int tid,
                                           const LoadCtx& lc, int k0)
{
#pragma unroll
    for (int i = 0; i < 4; i++) {          // A: 128 rows x 8 chunks of 16B
        int idx = tid + i * 256;
        int r = idx >> 3, c = idx & 7;
        uint32_t d = sbase + r * 128 + ((uint32_t)(c ^ (r & 7)) << 4);
        CP_ASYNC16(d, g_X + lc.xbase + (size_t)r * D_ + k0 + c * 8);
    }
#pragma unroll
    for (int i = 0; i < 4; i++) {          // B: 128 rows x 8 chunks of 16B
        int idx = tid + i * 256;
        int r = idx >> 3, c = idx & 7;
        uint32_t d = sbase + B_OFF + r * 128 + ((uint32_t)(c ^ (r & 7)) << 4);
        CP_ASYNC16(d, g_W + (size_t)(lc.nb * 128 + r) * KPAD + k0 + c * 8);
    }
}

__global__ __launch_bounds__(256, 2) void conv_hmma_kernel(
    const float* __restrict__ conv_b, const int* __restrict__ entity_pos)
{
    extern __shared__ char smem[];
    const uint32_t sb = smem_u32(smem);
    const int tid  = threadIdx.x;
    const int lane = tid & 31, wid = tid >> 5;
    const int wm = wid & 3, wn = wid >> 2;       // warp grid 4(M) x 2(N)
    const int nb = blockIdx.x;                    // filter quarter
    const int n  = blockIdx.y;                    // sentence

    float* biasS = reinterpret_cast<float*>(smem + SM_BIAS);
    if (tid < 128) biasS[tid] = conv_b[nb * 128 + tid];

    LoadCtx lc;
    lc.xbase = (size_t)n * (L_ * D_);
    lc.nb = nb;

    const int rowA = wm * 32 + ((lane >> 3) & 1) * 8 + (lane & 7);
    const int haA  = lane >> 4;
    const uint32_t offA = rowA * 128;
    const int saA = rowA & 7;
    const int rowB = wn * 64 + ((lane >> 4) & 1) * 8 + (lane & 7);
    const int hbB  = (lane >> 3) & 1;
    const uint32_t offB = rowB * 128;
    const int sbB = rowB & 7;

    float acc[2][8][4];
#pragma unroll
    for (int i = 0; i < 2; i++)
#pragma unroll
        for (int q = 0; q < 8; q++)
#pragma unroll
            for (int v = 0; v < 4; v++) acc[i][q][v] = 0.f;

    load_stage(sb, tid, lc, 0);
    CP_COMMIT();

    for (int kc = 0; kc < NKC; kc++) {
        if (kc + 1 < NKC) {
            load_stage(sb + ((kc + 1) & 1) * STAGE_SZ, tid, lc, (kc + 1) * KC);
            CP_COMMIT();
            CP_WAIT1();
        } else {
            CP_WAIT0();
        }
        __syncthreads();

        const uint32_t stg = sb + (kc & 1) * STAGE_SZ;
#pragma unroll
        for (int ks = 0; ks < 4; ks++) {
            uint32_t a[2][4];
#pragma unroll
            for (int i = 0; i < 2; i++) {
                uint32_t ad = stg + offA + i * 2048
                            + ((uint32_t)((ks * 2 + haA) ^ saA) << 4);
                LDSM_X4(a[i][0], a[i][1], a[i][2], a[i][3], ad);
            }
#pragma unroll
            for (int j = 0; j < 4; j++) {
                uint32_t b0, b1, b2, b3;
                uint32_t bd = stg + B_OFF + offB + j * 2048
                            + ((uint32_t)((ks * 2 + hbB) ^ sbB) << 4);
                LDSM_X4(b0, b1, b2, b3, bd);
#pragma unroll
                for (int i = 0; i < 2; i++) {
                    MMAF16(acc[i][j * 2],     a[i][0], a[i][1], a[i][2], a[i][3], b0, b1);
                    MMAF16(acc[i][j * 2 + 1], a[i][0], a[i][1], a[i][2], a[i][3], b2, b3);
                }
            }
        }
        __syncthreads();
    }

    // ---- epilogue: bias + tanh -> smem, then 3-segment max over t ----
    float* red = reinterpret_cast<float*>(smem);        // [128][RED_STR]
    const int r0b = wm * 32 + (lane >> 2);
    const int c0b = wn * 64 + (lane & 3) * 2;
#pragma unroll
    for (int i = 0; i < 2; i++) {
#pragma unroll
        for (int q = 0; q < 8; q++) {
            const int r0 = r0b + i * 16;
            const int c0 = c0b + q * 8;
            red[r0 * RED_STR + c0]           = tanhf(acc[i][q][0] + biasS[c0]);
            red[r0 * RED_STR + c0 + 1]       = tanhf(acc[i][q][1] + biasS[c0 + 1]);
            red[(r0 + 8) * RED_STR + c0]     = tanhf(acc[i][q][2] + biasS[c0]);
            red[(r0 + 8) * RED_STR + c0 + 1] = tanhf(acc[i][q][3] + biasS[c0 + 1]);
        }
    }
    __syncthreads();

    const int p1 = entity_pos[2 * n];
    const int p2 = entity_pos[2 * n + 1];
    float* part = red + 128 * RED_STR;                   // [2][3][128]
    {
        const int half = tid >> 7, c = tid & 127;
        const int t0 = half ? 64 : 0;
        const int t1 = half ? (LP_ - 1) : 63;
        float m0 = NEG_, m1 = NEG_, m2 = NEG_;
        for (int t = t0; t <= t1; t++) {
            float v = red[t * RED_STR + c];
            if (t <= p1) m0 = fmaxf(m0, v);
            if (t >= p1 && t <= p2) m1 = fmaxf(m1, v);
            if (t >= p2) m2 = fmaxf(m2, v);
        }
        part[(half * 3 + 0) * 128 + c] = m0;
        part[(half * 3 + 1) * 128 + c] = m1;
        part[(half * 3 + 2) * 128 + c] = m2;
    }
    __syncthreads();

    if (tid < 128) {
        const size_t fo = (size_t)n * F3 + (size_t)(nb * 128 + tid) * 3;
#pragma unroll
        for (int s = 0; s < 3; s++)
            g_feat[fo + s] = fmaxf(part[s * 128 + tid], part[(3 + s) * 128 + tid]);
    }
}

// ---------------------------------------------------------------------------
// Kernel 3: out[n][c] = feat[n] @ out_w + out_b, via padded wT [1536][64].
// 4 sentences per CTA; 4 j-groups x 64 c-lanes; weight loads coalesced and
// shared across 4 independent accumulator chains.
// ---------------------------------------------------------------------------
#define SPC 4
__global__ __launch_bounds__(256) void out_gemm_kernel(
    const float* __restrict__ out_b, float* __restrict__ out)
{
    __shared__ float sf[SPC * F3];                 // 24KB feats
    __shared__ float part[4][SPC][CP];             // 4KB partials
    const int n0 = blockIdx.x * SPC;

    // cooperative feat load: 4*1536 floats = 1536 float4, 6 per thread
    {
        const float4* src = reinterpret_cast<const float4*>(g_feat + (size_t)n0 * F3);
        float4* dst = reinterpret_cast<float4*>(sf);
        for (int i = threadIdx.x; i < SPC * F3 / 4; i += 256)
            dst[i] = src[i];
    }
    __syncthreads();

    const int g = threadIdx.x >> 6;                // j-group 0..3
    const int c = threadIdx.x & 63;                // class lane (pad to 64)
    float acc0 = 0.f, acc1 = 0.f, acc2 = 0.f, acc3 = 0.f;
    const int j0 = g * (F3 / 4);                   // 384 j per group
    const float* wp = g_wT + (size_t)j0 * CP + c;
#pragma unroll 4
    for (int j = 0; j < F3 / 4; j++) {
        const float w = wp[j * CP];
        const int jj = j0 + j;
        acc0 += sf[0 * F3 + jj] * w;
        acc1 += sf[1 * F3 + jj] * w;
        acc2 += sf[2 * F3 + jj] * w;
        acc3 += sf[3 * F3 + jj] * w;
    }
    part[g][0][c] = acc0;
    part[g][1][c] = acc1;
    part[g][2][c] = acc2;
    part[g][3][c] = acc3;
    __syncthreads();

    {
        const int s = threadIdx.x >> 6, cc = threadIdx.x & 63;
        if (cc < C_) {
            float v = part[0][s][cc] + part[1][s][cc] +
                      part[2][s][cc] + part[3][s][cc] + out_b[cc];
            out[(size_t)(n0 + s) * C_ + cc] = v;
        }
    }
}

// ---------------------------------------------------------------------------
// Launch. Inputs: tokens, pf1, pf2, entity_pos, wordvec, pf1_emb, pf2_emb,
// conv_w, conv_b, out_w, out_b.  Output: float32 [N, C].
// ---------------------------------------------------------------------------
extern "C" void kernel_launch(void* const* d_in, const int* in_sizes, int n_in,
                              void* d_out, int out_size)
{
    const int*   tokens     = (const int*)d_in[0];
    const int*   pf1        = (const int*)d_in[1];
    const int*   pf2        = (const int*)d_in[2];
    const int*   entity_pos = (const int*)d_in[3];
    const float* wordvec    = (const float*)d_in[4];
    const float* pf1_emb    = (const float*)d_in[5];
    const float* pf2_emb    = (const float*)d_in[6];
    const float* conv_w     = (const float*)d_in[7];
    const float* conv_b     = (const float*)d_in[8];
    const float* out_w      = (const float*)d_in[9];
    const float* out_b      = (const float*)d_in[10];
    float* out = (float*)d_out;

    cudaFuncSetAttribute(conv_hmma_kernel,
                         cudaFuncAttributeMaxDynamicSharedMemorySize, SM_DYN);

    gather_kernel<<<N_ * L_ / 2, 256>>>(tokens, pf1, pf2, wordvec, pf1_emb, pf2_emb);
    wconv_kernel<<<(NF_ * KPAD) / 256, 256>>>(conv_w);
    wt_kernel<<<(F3 * CP) / 256, 256>>>(out_w);
    conv_hmma_kernel<<<dim3(4, N_), 256, SM_DYN>>>(conv_b, entity_pos);
    out_gemm_kernel<<<N_ / SPC, 256>>>(out_b, out);
}